// round 3
// baseline (speedup 1.0000x reference)
#include <cuda_runtime.h>

// Problem constants (fixed shapes from the reference)
#define BB 256      // batch
#define NN 73728    // variables
#define KK 8        // messages per variable

// Scratch: transposed check matrix, (N, B) row-major. 75.5 MB, static device bss.
__device__ float g_checkT[(size_t)NN * BB];

// ---------------------------------------------------------------------------
// K1: tiled transpose  check (B,N) -> checkT (N,B)
// block (32,8), grid (N/32, B/32). Classic padded-smem transpose.
// ---------------------------------------------------------------------------
__global__ void __launch_bounds__(256) transpose_check_kernel(
    const float* __restrict__ check)
{
    __shared__ float tile[32][33];
    const int n0 = blockIdx.x * 32;
    const int b0 = blockIdx.y * 32;
    const int tx = threadIdx.x;   // 0..31
    const int ty = threadIdx.y;   // 0..7

    #pragma unroll
    for (int i = 0; i < 32; i += 8) {
        tile[ty + i][tx] = check[(size_t)(b0 + ty + i) * NN + (n0 + tx)];
    }
    __syncthreads();
    #pragma unroll
    for (int i = 0; i < 32; i += 8) {
        // out[n0+ty+i][b0+tx] = in[b0+tx][n0+ty+i]
        g_checkT[(size_t)(n0 + ty + i) * BB + (b0 + tx)] = tile[tx][ty + i];
    }
}

// ---------------------------------------------------------------------------
// K2: gather-sum + fused back-transpose.
// Each block owns a tile of 32 n-values and ALL 256 batch rows.
// Phase 1: thread = b; for each n in tile, sum 8 coalesced 1KB gather rows
//          from checkT into smem tile s_sum[n][b].
// Phase 2: warp w handles b-rows [w*32, w*32+32); lanes sweep n -> coalesced
//          llr read and out write in the original (B,N) layout.
// ---------------------------------------------------------------------------
__global__ void __launch_bounds__(256) gather_sum_kernel(
    const float* __restrict__ llr,
    const int* __restrict__ var_idx,        // (N, K) int32, -1 = invalid
    float* __restrict__ out)
{
    __shared__ int   s_idx[32 * KK];          // 1 KB
    __shared__ float s_sum[32][BB + 1];       // 32 x 257 floats ~= 32.9 KB

    const int n0  = blockIdx.x * 32;
    const int tid = threadIdx.x;              // 0..255

    // load index tile: 32 n * 8 k = 256 int32 -> one per thread, coalesced
    s_idx[tid] = var_idx[(size_t)n0 * KK + tid];
    __syncthreads();

    // Phase 1: coalesced gathers. All 256 threads share the same idx per
    // (n,k) -> uniform branch, no divergence; each warp-LDG reads 128B
    // contiguous from a checkT row (mostly L2-resident).
    // Indices hoisted into registers so the 8 gathers issue back-to-back
    // (MLP=8 covers the ~250-cycle L2 hit latency).
    #pragma unroll 4
    for (int i = 0; i < 32; i++) {
        int jj[KK];
        #pragma unroll
        for (int k = 0; k < KK; k++) jj[k] = s_idx[i * KK + k];

        float sum = 0.0f;
        #pragma unroll
        for (int k = 0; k < KK; k++) {
            if (jj[k] >= 0) {
                sum += __ldg(&g_checkT[(size_t)jj[k] * BB + tid]);
            }
        }
        s_sum[i][tid] = sum;
    }
    __syncthreads();

    // Phase 2: transposed writeback. lane -> n offset (coalesced gmem),
    // smem read stride 257 -> conflict-free.
    const int lane = tid & 31;
    const int w    = tid >> 5;                // 0..7
    const int n    = n0 + lane;
    #pragma unroll 4
    for (int bi = 0; bi < 32; bi++) {
        const int b = w * 32 + bi;
        const size_t g = (size_t)b * NN + n;
        out[g] = llr[g] + s_sum[lane][b];
    }
}

extern "C" void kernel_launch(void* const* d_in, const int* in_sizes, int n_in,
                              void* d_out, int out_size)
{
    const float* llr   = (const float*)d_in[0];   // (B, N) f32
    const float* check = (const float*)d_in[1];   // (B, N) f32
    const int*   vidx  = (const int*)d_in[2];     // (N, K) i32
    float*       out   = (float*)d_out;           // (B, N) f32
    (void)in_sizes; (void)n_in; (void)out_size;

    // K1: transpose check -> g_checkT
    dim3 tb(32, 8);
    dim3 tg(NN / 32, BB / 32);
    transpose_check_kernel<<<tg, tb>>>(check);

    // K2: gather + sum + fused output transpose
    gather_sum_kernel<<<NN / 32, 256>>>(llr, vidx, out);
}

// round 5
// speedup vs baseline: 1.1853x; 1.1853x over previous
#include <cuda_runtime.h>

// Problem constants (fixed shapes from the reference)
#define BB 256      // batch
#define NN 73728    // variables
#define KK 8        // messages per variable
#define NT 32       // n-tile per block in K2

// Scratch: transposed check matrix, (N, B) row-major. 75.5 MB, static device bss.
__device__ __align__(16) float g_checkT[(size_t)NN * BB];

// ---------------------------------------------------------------------------
// K1: tiled transpose  check (B,N) -> checkT (N,B).
// Vector LDG.128 / STG.128 on gmem; scalar smem ops (conflict-free, and no
// 16B-alignment hazard with the 33-float row padding).
// block (8,32): tx = float4 column, ty = row.
// ---------------------------------------------------------------------------
__global__ void __launch_bounds__(256) transpose_check_kernel(
    const float* __restrict__ check)
{
    __shared__ float tile[32][33];
    const int n0 = blockIdx.x * 32;
    const int b0 = blockIdx.y * 32;
    const int tx = threadIdx.x;   // 0..7
    const int ty = threadIdx.y;   // 0..31

    // load: row b0+ty, float4 at n0+4tx  (8 lanes x 16B = 128B contiguous/row)
    const float4 in4 = *(const float4*)&check[(size_t)(b0 + ty) * NN + (n0 + 4 * tx)];
    tile[ty][4 * tx + 0] = in4.x;   // bank (ty + 4tx + c) % 32: all distinct
    tile[ty][4 * tx + 1] = in4.y;
    tile[ty][4 * tx + 2] = in4.z;
    tile[ty][4 * tx + 3] = in4.w;
    __syncthreads();

    // store: row n0+ty of checkT, float4 of b at b0+4tx
    float4 o;
    o.x = tile[4 * tx + 0][ty];     // bank (4tx + c + ty) % 32: all distinct
    o.y = tile[4 * tx + 1][ty];
    o.z = tile[4 * tx + 2][ty];
    o.w = tile[4 * tx + 3][ty];
    *(float4*)&g_checkT[(size_t)(n0 + ty) * BB + (b0 + 4 * tx)] = o;
}

// ---------------------------------------------------------------------------
// K2: gather-sum + fused back-transpose, float4 gather.
// Phase 1: thread (sub = tid/64, bq = tid%64). For its 8 n-values, sums 8
//          float4 gathers (LDG.128, 64 threads span each 1KB checkT row).
// Phase 2: warp w writes b-rows [w*32, w*32+32); lanes sweep n -> coalesced.
// ---------------------------------------------------------------------------
__global__ void __launch_bounds__(256) gather_sum_kernel(
    const float* __restrict__ llr,
    const int* __restrict__ var_idx,        // (N, K) int32, -1 = invalid
    float* __restrict__ out)
{
    __shared__ int s_idx[NT * KK];                       // 1 KB
    __shared__ __align__(16) float s_sum[NT][260];       // 33.3 KB, row = 1040B (16B-divisible)

    const int n0  = blockIdx.x * NT;
    const int tid = threadIdx.x;              // 0..255

    // index tile: 32 n * 8 k = 256 int32 -> one per thread, coalesced
    s_idx[tid] = var_idx[(size_t)n0 * KK + tid];
    __syncthreads();

    const int sub = tid >> 6;                 // 0..3  (n interleave)
    const int bq  = tid & 63;                 // float4 index over b
    const float4* __restrict__ cT4 = (const float4*)g_checkT;

    #pragma unroll
    for (int i = 0; i < NT / 4; i++) {
        const int nl = i * 4 + sub;
        int jj[KK];
        #pragma unroll
        for (int k = 0; k < KK; k++) jj[k] = s_idx[nl * KK + k];

        float4 s = make_float4(0.f, 0.f, 0.f, 0.f);
        #pragma unroll
        for (int k = 0; k < KK; k++) {
            if (jj[k] >= 0) {
                const float4 v = __ldg(&cT4[(size_t)jj[k] * (BB / 4) + bq]);
                s.x += v.x; s.y += v.y; s.z += v.z; s.w += v.w;
            }
        }
        // STS.128 at word 260*nl + 4*bq: 16B-aligned, consecutive bq -> conflict-free
        *(float4*)&s_sum[nl][4 * bq] = s;
    }
    __syncthreads();

    // Phase 2: transposed writeback. lane -> n (coalesced gmem).
    const int lane = tid & 31;
    const int w    = tid >> 5;                // 0..7
    const int n    = n0 + lane;
    #pragma unroll 4
    for (int bi = 0; bi < 32; bi++) {
        const int b = w * 32 + bi;
        const size_t g = (size_t)b * NN + n;
        out[g] = llr[g] + s_sum[lane][b];
    }
}

extern "C" void kernel_launch(void* const* d_in, const int* in_sizes, int n_in,
                              void* d_out, int out_size)
{
    const float* llr   = (const float*)d_in[0];   // (B, N) f32
    const float* check = (const float*)d_in[1];   // (B, N) f32
    const int*   vidx  = (const int*)d_in[2];     // (N, K) i32
    float*       out   = (float*)d_out;           // (B, N) f32
    (void)in_sizes; (void)n_in; (void)out_size;

    // K1: transpose check -> g_checkT
    dim3 tb(8, 32);
    dim3 tg(NN / 32, BB / 32);
    transpose_check_kernel<<<tg, tb>>>(check);

    // K2: gather + sum + fused output transpose
    gather_sum_kernel<<<NN / NT, 256>>>(llr, vidx, out);
}

// round 6
// speedup vs baseline: 1.4711x; 1.2410x over previous
#include <cuda_runtime.h>

// Problem constants (fixed shapes from the reference)
#define BB 256      // batch
#define NN 73728    // variables
#define KK 8        // messages per variable
#define NT 32       // n-tile per block in K2

// Scratch: transposed check matrix, (N, B) row-major. 75.5 MB, static device bss.
__device__ __align__(16) float g_checkT[(size_t)NN * BB];

// ---------------------------------------------------------------------------
// K1: tiled transpose  check (B,N) -> checkT (N,B).
// Vector LDG.128 / STG.128 on gmem; scalar smem ops (conflict-free, no 16B
// alignment hazard with the 33-float row padding).
// block (8,32): tx = float4 column, ty = row.
// ---------------------------------------------------------------------------
__global__ void __launch_bounds__(256) transpose_check_kernel(
    const float* __restrict__ check)
{
    __shared__ float tile[32][33];
    const int n0 = blockIdx.x * 32;
    const int b0 = blockIdx.y * 32;
    const int tx = threadIdx.x;   // 0..7
    const int ty = threadIdx.y;   // 0..31

    const float4 in4 = *(const float4*)&check[(size_t)(b0 + ty) * NN + (n0 + 4 * tx)];
    tile[ty][4 * tx + 0] = in4.x;   // bank (ty + 4tx + c) % 32: all distinct
    tile[ty][4 * tx + 1] = in4.y;
    tile[ty][4 * tx + 2] = in4.z;
    tile[ty][4 * tx + 3] = in4.w;
    __syncthreads();

    float4 o;
    o.x = tile[4 * tx + 0][ty];     // bank (4tx + c + ty) % 32: all distinct
    o.y = tile[4 * tx + 1][ty];
    o.z = tile[4 * tx + 2][ty];
    o.w = tile[4 * tx + 3][ty];
    *(float4*)&g_checkT[(size_t)(n0 + ty) * BB + (b0 + 4 * tx)] = o;
}

// ---------------------------------------------------------------------------
// K2: gather-sum + fused back-transpose, float4 gather, 512 threads/block.
// 512 thr x 34.3KB smem -> 4 blocks/SM = 64 warps = 100% occupancy
// (vs 48 warps at 256 thr) -> more outstanding gathers to hide L2/DRAM latency.
// Phase 1: thread (sub = tid/64 in 0..7, bq = tid%64). For its 4 n-values,
//          sums 8 float4 gathers each (LDG.128; 64 threads span a 1KB row).
// Phase 2: warp w writes b-rows [w*16, w*16+16); lanes sweep n -> coalesced.
// ---------------------------------------------------------------------------
__global__ void __launch_bounds__(512) gather_sum_kernel(
    const float* __restrict__ llr,
    const int* __restrict__ var_idx,        // (N, K) int32, -1 = invalid
    float* __restrict__ out)
{
    __shared__ int s_idx[NT * KK];                       // 1 KB
    __shared__ __align__(16) float s_sum[NT][260];       // 33.3 KB, row = 1040B (16B-divisible)

    const int n0  = blockIdx.x * NT;
    const int tid = threadIdx.x;              // 0..511

    // index tile: 32 n * 8 k = 256 int32, first 256 threads load, coalesced
    if (tid < NT * KK) s_idx[tid] = var_idx[(size_t)n0 * KK + tid];
    __syncthreads();

    const int sub = tid >> 6;                 // 0..7  (n interleave)
    const int bq  = tid & 63;                 // float4 index over b
    const float4* __restrict__ cT4 = (const float4*)g_checkT;

    #pragma unroll
    for (int i = 0; i < NT / 8; i++) {        // 4 iterations
        const int nl = i * 8 + sub;
        int jj[KK];
        #pragma unroll
        for (int k = 0; k < KK; k++) jj[k] = s_idx[nl * KK + k];

        float4 s = make_float4(0.f, 0.f, 0.f, 0.f);
        #pragma unroll
        for (int k = 0; k < KK; k++) {
            if (jj[k] >= 0) {
                const float4 v = __ldg(&cT4[(size_t)jj[k] * (BB / 4) + bq]);
                s.x += v.x; s.y += v.y; s.z += v.z; s.w += v.w;
            }
        }
        // STS.128 at word 260*nl + 4*bq: 16B-aligned, consecutive bq -> conflict-free
        *(float4*)&s_sum[nl][4 * bq] = s;
    }
    __syncthreads();

    // Phase 2: transposed writeback. lane -> n (coalesced gmem).
    const int lane = tid & 31;
    const int w    = tid >> 5;                // 0..15
    const int n    = n0 + lane;
    #pragma unroll 4
    for (int bi = 0; bi < 16; bi++) {
        const int b = w * 16 + bi;
        const size_t g = (size_t)b * NN + n;
        out[g] = llr[g] + s_sum[lane][b];
    }
}

extern "C" void kernel_launch(void* const* d_in, const int* in_sizes, int n_in,
                              void* d_out, int out_size)
{
    const float* llr   = (const float*)d_in[0];   // (B, N) f32
    const float* check = (const float*)d_in[1];   // (B, N) f32
    const int*   vidx  = (const int*)d_in[2];     // (N, K) i32
    float*       out   = (float*)d_out;           // (B, N) f32
    (void)in_sizes; (void)n_in; (void)out_size;

    // K1: transpose check -> g_checkT
    dim3 tb(8, 32);
    dim3 tg(NN / 32, BB / 32);
    transpose_check_kernel<<<tg, tb>>>(check);

    // K2: gather + sum + fused output transpose
    gather_sum_kernel<<<NN / NT, 512>>>(llr, vidx, out);
}